// round 2
// baseline (speedup 1.0000x reference)
#include <cuda_runtime.h>
#include <math.h>

// Problem dims (fixed by the reference)
#define TT 128
#define BB 32
#define EE 512
#define HH 1024
#define VV 32000
#define GG (3 * HH)       // 3072
#define MM (TT * BB)      // 4096

// ---------------- scratch (device globals; no allocations at launch) --------
__device__ float g_gx[MM * GG];        // [T*B, 3H] input-side gate preacts (~50 MB)
__device__ float g_hall[MM * HH];      // [T*B, H] all hidden states (~17 MB)
__device__ float g_h[2][BB * HH];      // ping-pong hidden state

// ---------------- generic fp32 SGEMM: C = A * B^T + bias --------------------
// A: [M,K] row-major (optionally row-gathered through `gather` as the shifted
//    token indices into the embedding table), B: [N,K] row-major, bias: [N].
// BM=BN=128, BK=8, 256 threads, 8x8 per-thread microtile.
__global__ __launch_bounds__(256)
void sgemm128(const float* __restrict__ A, const float* __restrict__ Bm,
              const float* __restrict__ bias, float* __restrict__ C,
              int M, int N, int K, const int* __restrict__ gather)
{
    __shared__ float As[8][128];
    __shared__ float Bs[8][128];

    const int bm = blockIdx.y * 128;
    const int bn = blockIdx.x * 128;
    const int tid = threadIdx.x;

    // staging: each thread loads one float4 of A and one of B per K-slab
    const int lr = tid >> 1;            // 0..127 row within tile
    const int lc = (tid & 1) << 2;      // 0 or 4 within K-slab

    const int am = bm + lr;
    const float* arow;
    if (gather) {
        // x_idx[t][b] = inputs[max(t-1,0)][b];  m = t*B + b
        int r = (am < BB) ? gather[am] : gather[am - BB];
        arow = A + (size_t)r * K;
    } else {
        arow = A + (size_t)am * K;
    }
    const float* brow = Bm + (size_t)(bn + lr) * K;

    const int tx = tid & 15;            // 16 columns of threads
    const int ty = tid >> 4;            // 16 rows of threads

    float acc[8][8];
#pragma unroll
    for (int i = 0; i < 8; i++)
#pragma unroll
        for (int j = 0; j < 8; j++) acc[i][j] = 0.f;

    for (int k0 = 0; k0 < K; k0 += 8) {
        float4 av = *(const float4*)(arow + k0 + lc);
        float4 bv = *(const float4*)(brow + k0 + lc);
        As[lc + 0][lr] = av.x; As[lc + 1][lr] = av.y;
        As[lc + 2][lr] = av.z; As[lc + 3][lr] = av.w;
        Bs[lc + 0][lr] = bv.x; Bs[lc + 1][lr] = bv.y;
        Bs[lc + 2][lr] = bv.z; Bs[lc + 3][lr] = bv.w;
        __syncthreads();

#pragma unroll
        for (int k = 0; k < 8; k++) {
            float a[8], b[8];
            *(float4*)(a)     = *(const float4*)(&As[k][ty * 8]);
            *(float4*)(a + 4) = *(const float4*)(&As[k][ty * 8 + 4]);
            *(float4*)(b)     = *(const float4*)(&Bs[k][tx * 8]);
            *(float4*)(b + 4) = *(const float4*)(&Bs[k][tx * 8 + 4]);
#pragma unroll
            for (int i = 0; i < 8; i++)
#pragma unroll
                for (int j = 0; j < 8; j++)
                    acc[i][j] += a[i] * b[j];
        }
        __syncthreads();
    }

#pragma unroll
    for (int i = 0; i < 8; i++) {
        const int row = bm + ty * 8 + i;
        float* crow = C + (size_t)row * N + bn + tx * 8;
#pragma unroll
        for (int j = 0; j < 8; j++)
            crow[j] = acc[i][j] + bias[bn + tx * 8 + j];
    }
}

// ---------------- one GRU step (fused GEMV + pointwise) ---------------------
// grid = 128 CTAs x 256 threads. CTA c owns hidden units j in [8c, 8c+8);
// warp w -> unit j = 8c + w; lane l -> batch b = l.
// h (32x1024 fp32) is staged in smem with pitch 1028 floats:
//   byte stride 4112 = 16*257 -> 16B-slot index (257*l + k/4) mod 8 == (l+k/4) mod 8
//   => LDS.128 along k is bank-conflict-free for all lanes.
// w_hh rows stream from L2 as warp-uniform (broadcast) LDG.128.
#define HP 1028

__global__ __launch_bounds__(256)
void gru_step(const float* __restrict__ h_in,     // [B,H] or nullptr (h0 = 0)
              const float* __restrict__ w_hh,     // [3H,H]
              const float* __restrict__ b_hh,     // [3H]
              const float* __restrict__ gx_t,     // [B,3H] slab for this t
              float* __restrict__ h_out,          // [B,H]
              float* __restrict__ out_t,          // g_hall slab for this t
              float* __restrict__ hid_out)        // final-hidden dst or nullptr
{
    extern __shared__ float h_s[];                // [32][HP]
    const int tid = threadIdx.x;

    if (h_in) {
        for (int i = tid; i < BB * (HH / 4); i += 256) {
            int b  = i >> 8;                       // 256 float4 per batch row
            int k4 = i & 255;
            float4 v = *(const float4*)(h_in + b * HH + k4 * 4);
            *(float4*)&h_s[b * HP + k4 * 4] = v;
        }
    } else {
        for (int i = tid; i < BB * (HH / 4); i += 256) {
            int b  = i >> 8;
            int k4 = i & 255;
            *(float4*)&h_s[b * HP + k4 * 4] = make_float4(0.f, 0.f, 0.f, 0.f);
        }
    }
    __syncthreads();

    const int w = tid >> 5;                        // warp -> unit offset
    const int l = tid & 31;                        // lane -> batch
    const int j = blockIdx.x * 8 + w;              // hidden unit

    const float* wr = w_hh + (size_t)j * HH;
    const float* wz = w_hh + (size_t)(HH + j) * HH;
    const float* wn = w_hh + (size_t)(2 * HH + j) * HH;
    const float* hb = &h_s[l * HP];

    float ar = 0.f, az = 0.f, an = 0.f;
#pragma unroll 8
    for (int k = 0; k < HH; k += 4) {
        float4 hv = *(const float4*)(hb + k);
        float4 r4 = *(const float4*)(wr + k);      // warp-uniform broadcast
        float4 z4 = *(const float4*)(wz + k);
        float4 n4 = *(const float4*)(wn + k);
        ar += hv.x * r4.x + hv.y * r4.y + hv.z * r4.z + hv.w * r4.w;
        az += hv.x * z4.x + hv.y * z4.y + hv.z * z4.z + hv.w * z4.w;
        an += hv.x * n4.x + hv.y * n4.y + hv.z * n4.z + hv.w * n4.w;
    }

    const float xr = gx_t[l * GG + j];
    const float xz = gx_t[l * GG + HH + j];
    const float xn = gx_t[l * GG + 2 * HH + j];
    const float hr = ar + b_hh[j];
    const float hz = az + b_hh[HH + j];
    const float hn = an + b_hh[2 * HH + j];

    const float r = 1.f / (1.f + expf(-(xr + hr)));
    const float z = 1.f / (1.f + expf(-(xz + hz)));
    const float n = tanhf(xn + r * hn);
    const float hold = h_s[l * HP + j];
    const float hnew = (1.f - z) * n + z * hold;

    h_out[l * HH + j] = hnew;
    out_t[l * HH + j] = hnew;
    if (hid_out) hid_out[l * HH + j] = hnew;
}

// ---------------- launch --------------------------------------------------
extern "C" void kernel_launch(void* const* d_in, const int* in_sizes, int n_in,
                              void* d_out, int out_size)
{
    // metadata order (setup_inputs dict order):
    const int*   inputs = (const int*)  d_in[0];   // [T,B] int32
    // d_in[1] encoder_output (unused), d_in[2] encoder_mask (unused)
    const float* emb    = (const float*)d_in[3];   // [V,E]
    const float* w_ih   = (const float*)d_in[4];   // [3H,E]
    const float* w_hh   = (const float*)d_in[5];   // [3H,H]
    const float* b_ih   = (const float*)d_in[6];   // [3H]
    const float* b_hh   = (const float*)d_in[7];   // [3H]
    const float* out_w  = (const float*)d_in[8];   // [V,H]
    const float* out_b  = (const float*)d_in[9];   // [V]

    float* logits = (float*)d_out;                          // [T,B,V]
    float* hidden = (float*)d_out + (size_t)MM * VV;        // [1,B,H]

    float* gx   = nullptr;  cudaGetSymbolAddress((void**)&gx,   g_gx);
    float* hall = nullptr;  cudaGetSymbolAddress((void**)&hall, g_hall);
    float* hbuf = nullptr;  cudaGetSymbolAddress((void**)&hbuf, g_h);

    // 1) gx = emb[x_idx] @ w_ih^T + b_ih    (fused gather GEMM)
    {
        dim3 grid(GG / 128, MM / 128);   // (24, 32)
        sgemm128<<<grid, 256>>>(emb, w_ih, b_ih, gx, MM, GG, EE, inputs);
    }

    // 2) 128 sequential GRU steps
    const int smem = BB * HP * sizeof(float);   // 131584 B
    cudaFuncSetAttribute(gru_step, cudaFuncAttributeMaxDynamicSharedMemorySize, smem);
    for (int t = 0; t < TT; t++) {
        const float* hin = (t == 0) ? nullptr : hbuf + (t & 1) * (BB * HH);
        float* hout = hbuf + ((t + 1) & 1) * (BB * HH);
        float* hid  = (t == TT - 1) ? hidden : nullptr;
        gru_step<<<128, 256, smem>>>(hin, w_hh, b_hh,
                                     gx + (size_t)t * BB * GG,
                                     hout,
                                     hall + (size_t)t * BB * HH,
                                     hid);
    }

    // 3) logits = hall @ out_w^T + out_b
    {
        dim3 grid(VV / 128, MM / 128);   // (250, 32)
        sgemm128<<<grid, 256>>>(hall, out_w, out_b, logits, MM, VV, HH, nullptr);
    }
}

// round 3
// speedup vs baseline: 1.2750x; 1.2750x over previous
#include <cuda_runtime.h>
#include <math.h>

// Problem dims (fixed by the reference)
#define TT 128
#define BB 32
#define EE 512
#define HH 1024
#define VV 32000
#define GG (3 * HH)       // 3072
#define MM (TT * BB)      // 4096
#define NCTA 128

// ---------------- scratch (device globals; no allocations at launch) --------
__device__ float g_gx[MM * GG];        // [T*B, 3H] input-side gate preacts (~50 MB)
__device__ float g_hall[MM * HH];      // [T*B, H] all hidden states (~17 MB)
__device__ float g_hT[2][HH * BB];     // ping-pong hidden state, TRANSPOSED [j][b]
__device__ unsigned g_cnt = 0;         // grid barrier arrival counter
__device__ unsigned g_gen = 0;         // grid barrier generation (monotonic)

__device__ __forceinline__ unsigned ld_acq(unsigned* p) {
    unsigned v;
    asm volatile("ld.acquire.gpu.u32 %0, [%1];" : "=r"(v) : "l"(p) : "memory");
    return v;
}
__device__ __forceinline__ float ldcg(const float* p) {
    float v;
    asm volatile("ld.global.cg.f32 %0, [%1];" : "=f"(v) : "l"(p));
    return v;
}
__device__ __forceinline__ float4 ldcg4(const float4* p) {
    float4 v;
    asm volatile("ld.global.cg.v4.f32 {%0,%1,%2,%3}, [%4];"
                 : "=f"(v.x), "=f"(v.y), "=f"(v.z), "=f"(v.w) : "l"(p));
    return v;
}

// ---------------- generic fp32 SGEMM: C = A * B^T + bias --------------------
__global__ __launch_bounds__(256)
void sgemm128(const float* __restrict__ A, const float* __restrict__ Bm,
              const float* __restrict__ bias, float* __restrict__ C,
              int M, int N, int K, const int* __restrict__ gather)
{
    __shared__ float As[8][128];
    __shared__ float Bs[8][128];

    const int bm = blockIdx.y * 128;
    const int bn = blockIdx.x * 128;
    const int tid = threadIdx.x;

    const int lr = tid >> 1;
    const int lc = (tid & 1) << 2;

    const int am = bm + lr;
    const float* arow;
    if (gather) {
        int r = (am < BB) ? gather[am] : gather[am - BB];
        arow = A + (size_t)r * K;
    } else {
        arow = A + (size_t)am * K;
    }
    const float* brow = Bm + (size_t)(bn + lr) * K;

    const int tx = tid & 15;
    const int ty = tid >> 4;

    float acc[8][8];
#pragma unroll
    for (int i = 0; i < 8; i++)
#pragma unroll
        for (int j = 0; j < 8; j++) acc[i][j] = 0.f;

    for (int k0 = 0; k0 < K; k0 += 8) {
        float4 av = *(const float4*)(arow + k0 + lc);
        float4 bv = *(const float4*)(brow + k0 + lc);
        As[lc + 0][lr] = av.x; As[lc + 1][lr] = av.y;
        As[lc + 2][lr] = av.z; As[lc + 3][lr] = av.w;
        Bs[lc + 0][lr] = bv.x; Bs[lc + 1][lr] = bv.y;
        Bs[lc + 2][lr] = bv.z; Bs[lc + 3][lr] = bv.w;
        __syncthreads();

#pragma unroll
        for (int k = 0; k < 8; k++) {
            float a[8], b[8];
            *(float4*)(a)     = *(const float4*)(&As[k][ty * 8]);
            *(float4*)(a + 4) = *(const float4*)(&As[k][ty * 8 + 4]);
            *(float4*)(b)     = *(const float4*)(&Bs[k][tx * 8]);
            *(float4*)(b + 4) = *(const float4*)(&Bs[k][tx * 8 + 4]);
#pragma unroll
            for (int i = 0; i < 8; i++)
#pragma unroll
                for (int j = 0; j < 8; j++)
                    acc[i][j] += a[i] * b[j];
        }
        __syncthreads();
    }

#pragma unroll
    for (int i = 0; i < 8; i++) {
        const int row = bm + ty * 8 + i;
        float* crow = C + (size_t)row * N + bn + tx * 8;
#pragma unroll
        for (int j = 0; j < 8; j++)
            crow[j] = acc[i][j] + bias[bn + tx * 8 + j];
    }
}

// ---------------- persistent GRU recurrence ---------------------------------
// 128 CTAs x 256 threads, one CTA per SM (smem-limited to occ 1, grid <= 148
// SMs => all co-resident => custom grid barrier is deadlock-free).
// CTA c owns hidden units j in [8c, 8c+8). smem holds:
//   w_s [8 units][3 gates][1024 k]  = 96 KB   (loaded once from DRAM)
//   h_s [1024 k][32 b] (transposed) = 128 KB  (reloaded from L2 per step)
// Warp w: unit-pair p = w&3 (units 8c+2p, 8c+2p+1), k-half kh = w>>2.
// Lane: kg = lane>>3 (k quarter within half, interleaved by 4-float chunks),
//       bg = lane&7 (4 batches). Register tile 2 units x 3 gates x 4 batches.
__global__ __launch_bounds__(256, 1)
void gru_persistent(const float* __restrict__ w_hh,
                    const float* __restrict__ b_hh,
                    const float* __restrict__ gx,
                    float* __restrict__ hall,
                    float* __restrict__ hidden)
{
    extern __shared__ float smem[];
    float* w_s = smem;                 // 24*1024 floats
    float* h_s = smem + 24 * 1024;     // 1024*32 floats
    float* red = h_s;                  // reduction scratch aliases h_s (see below)

    const int tid = threadIdx.x;
    const int c = blockIdx.x;

    // ---- one-time: load this CTA's 24 w_hh rows into smem (coalesced) ----
    for (int idx = tid; idx < 24 * 256; idx += 256) {
        int r = idx >> 8;              // local row 0..23: unit uu=r/3, gate g=r%3
        int kq = idx & 255;
        int uu = r / 3, g = r % 3;
        int j = c * 8 + uu;
        float4 v = *(const float4*)(w_hh + ((size_t)(g * HH + j)) * HH + kq * 4);
        *(float4*)&w_s[r * HH + kq * 4] = v;
    }
    // ---- t=0 hidden state is zero ----
    for (int idx = tid; idx < HH * (BB / 4); idx += 256)
        *(float4*)&h_s[idx * 4] = make_float4(0.f, 0.f, 0.f, 0.f);
    __syncthreads();

    const int warp = tid >> 5, lane = tid & 31;
    const int pair = warp & 3, khalf = warp >> 2;
    const int kg = lane >> 3, bg = lane & 7;
    const int j0 = c * 8 + pair * 2;

    // biases for this warp's two units
    float bh[2][3];
#pragma unroll
    for (int u = 0; u < 2; u++)
#pragma unroll
        for (int g = 0; g < 3; g++)
            bh[u][g] = b_hh[g * HH + j0 + u];

    unsigned gen_base = 0;
    if (tid == 0) gen_base = ld_acq(&g_gen);

    float* hT = nullptr;   // set per step

    for (int t = 0; t < TT; t++) {
        // ---------------- dot products: gh = h @ w_hh^T ----------------
        float acc[2][3][4];
#pragma unroll
        for (int u = 0; u < 2; u++)
#pragma unroll
            for (int g = 0; g < 3; g++)
#pragma unroll
                for (int b = 0; b < 4; b++) acc[u][g][b] = 0.f;

        const int kofs = khalf * 512 + kg * 4;
        const float* w0 = &w_s[(pair * 2 + 0) * 3 * HH];
        const float* w1 = &w_s[(pair * 2 + 1) * 3 * HH];

        for (int i = 0; i < 32; i++) {
            const int k = kofs + i * 16;
            float hm[4][4];   // [m = k offset][b]
#pragma unroll
            for (int m = 0; m < 4; m++)
                *(float4*)hm[m] = *(const float4*)&h_s[(k + m) * BB + bg * 4];
            float wv[2][3][4];
#pragma unroll
            for (int g = 0; g < 3; g++) {
                *(float4*)wv[0][g] = *(const float4*)&w0[g * HH + k];
                *(float4*)wv[1][g] = *(const float4*)&w1[g * HH + k];
            }
#pragma unroll
            for (int u = 0; u < 2; u++)
#pragma unroll
                for (int g = 0; g < 3; g++)
#pragma unroll
                    for (int b = 0; b < 4; b++)
                        acc[u][g][b] += hm[0][b] * wv[u][g][0]
                                      + hm[1][b] * wv[u][g][1]
                                      + hm[2][b] * wv[u][g][2]
                                      + hm[3][b] * wv[u][g][3];
        }

        // reduce over kg (lanes l, l^8, l^16, l^24 share bg)
#pragma unroll
        for (int u = 0; u < 2; u++)
#pragma unroll
            for (int g = 0; g < 3; g++)
#pragma unroll
                for (int b = 0; b < 4; b++) {
                    float v = acc[u][g][b];
                    v += __shfl_xor_sync(0xffffffffu, v, 8);
                    v += __shfl_xor_sync(0xffffffffu, v, 16);
                    acc[u][g][b] = v;
                }

        // snapshot h_old before red aliases h_s
        float hold[2][4];
        if (lane < 8) {
#pragma unroll
            for (int u = 0; u < 2; u++)
#pragma unroll
                for (int b = 0; b < 4; b++)
                    hold[u][b] = h_s[(j0 + u) * BB + bg * 4 + b];
        }
        __syncthreads();

        // cross k-half reduction through smem (reuses h_s[0..767])
        if (khalf == 1 && lane < 8) {
#pragma unroll
            for (int u = 0; u < 2; u++)
#pragma unroll
                for (int g = 0; g < 3; g++)
#pragma unroll
                    for (int b = 0; b < 4; b++)
                        red[pair * 192 + bg * 24 + u * 12 + g * 4 + b] = acc[u][g][b];
        }
        __syncthreads();

        if (khalf == 0 && lane < 8) {
#pragma unroll
            for (int u = 0; u < 2; u++) {
                const int j = j0 + u;
#pragma unroll
                for (int b4 = 0; b4 < 4; b4++) {
                    const int b = bg * 4 + b4;
                    float hr = acc[u][0][b4] + red[pair * 192 + bg * 24 + u * 12 + 0 * 4 + b4] + bh[u][0];
                    float hz = acc[u][1][b4] + red[pair * 192 + bg * 24 + u * 12 + 1 * 4 + b4] + bh[u][1];
                    float hn = acc[u][2][b4] + red[pair * 192 + bg * 24 + u * 12 + 2 * 4 + b4] + bh[u][2];

                    const float* gxp = gx + ((size_t)t * BB + b) * GG;
                    float xr = gxp[j];
                    float xz = gxp[HH + j];
                    float xn = gxp[2 * HH + j];

                    float r = 1.f / (1.f + expf(-(xr + hr)));
                    float z = 1.f / (1.f + expf(-(xz + hz)));
                    float n = tanhf(xn + r * hn);
                    float hnew = (1.f - z) * n + z * hold[u][b4];

                    hall[((size_t)t * BB + b) * HH + j] = hnew;          // for logits GEMM
                    g_hT[t & 1][j * BB + b] = hnew;                      // for next step
                    if (t == TT - 1) hidden[b * HH + j] = hnew;          // final hidden
                }
            }
        }

        // ---------------- grid barrier ----------------
        __threadfence();
        __syncthreads();
        if (tid == 0) {
            if (atomicAdd(&g_cnt, 1u) == NCTA - 1) {
                atomicExch(&g_cnt, 0u);
                __threadfence();
                atomicAdd(&g_gen, 1u);
            }
            unsigned target = gen_base + (unsigned)(t + 1);
            while ((int)(ld_acq(&g_gen) - target) < 0) {}
        }
        __syncthreads();

        // ---------------- load next-step h (transposed) from L2 ----------------
        if (t < TT - 1) {
            hT = &g_hT[t & 1][0];
            for (int idx = tid; idx < HH * (BB / 4); idx += 256) {
                float4 v = ldcg4((const float4*)(hT + idx * 4));   // bypass stale L1
                *(float4*)&h_s[idx * 4] = v;
            }
            __syncthreads();
        }
    }
}

// ---------------- launch --------------------------------------------------
extern "C" void kernel_launch(void* const* d_in, const int* in_sizes, int n_in,
                              void* d_out, int out_size)
{
    const int*   inputs = (const int*)  d_in[0];   // [T,B] int32
    const float* emb    = (const float*)d_in[3];   // [V,E]
    const float* w_ih   = (const float*)d_in[4];   // [3H,E]
    const float* w_hh   = (const float*)d_in[5];   // [3H,H]
    const float* b_ih   = (const float*)d_in[6];   // [3H]
    const float* b_hh   = (const float*)d_in[7];   // [3H]
    const float* out_w  = (const float*)d_in[8];   // [V,H]
    const float* out_b  = (const float*)d_in[9];   // [V]

    float* logits = (float*)d_out;
    float* hidden = (float*)d_out + (size_t)MM * VV;

    float* gx   = nullptr;  cudaGetSymbolAddress((void**)&gx,   g_gx);
    float* hall = nullptr;  cudaGetSymbolAddress((void**)&hall, g_hall);

    // 1) gx = emb[x_idx] @ w_ih^T + b_ih
    {
        dim3 grid(GG / 128, MM / 128);
        sgemm128<<<grid, 256>>>(emb, w_ih, b_ih, gx, MM, GG, EE, inputs);
    }

    // 2) entire GRU recurrence in ONE persistent kernel
    {
        const int smem = (24 * HH + HH * BB) * sizeof(float);   // 98304+131072=229376
        cudaFuncSetAttribute(gru_persistent,
                             cudaFuncAttributeMaxDynamicSharedMemorySize, smem);
        gru_persistent<<<NCTA, 256, smem>>>(w_hh, b_hh, gx, hall, hidden);
    }

    // 3) logits = hall @ out_w^T + out_b
    {
        dim3 grid(VV / 128, MM / 128);
        sgemm128<<<grid, 256>>>(hall, out_w, out_b, logits, MM, VV, HH, nullptr);
    }
}

// round 5
// speedup vs baseline: 2.9753x; 2.3337x over previous
#include <cuda_runtime.h>
#include <cuda_bf16.h>
#include <math.h>
#include <stdint.h>

// Problem dims
#define TT 128
#define BB 32
#define EE 512
#define HH 1024
#define VV 32000
#define GG (3 * HH)       // 3072
#define MM (TT * BB)      // 4096
#define NCTA 128

// ---------------- scratch (device globals) ----------------------------------
__device__ float g_gx[MM * GG];                // [T*B, 3H]
__device__ float g_hall[MM * HH];              // [T*B, H]
__device__ float g_hT[2][HH * BB];             // ping-pong transposed hidden
__device__ unsigned g_cnt = 0;
__device__ unsigned g_gen = 0;
__device__ __nv_bfloat16 g_Ah[VV * EE];        // emb split, then hall split
__device__ __nv_bfloat16 g_Al[VV * EE];
__device__ __nv_bfloat16 g_Bh[VV * HH];        // out_w split
__device__ __nv_bfloat16 g_Bl[VV * HH];
__device__ __nv_bfloat16 g_Wh[GG * EE];        // w_ih split
__device__ __nv_bfloat16 g_Wl[GG * EE];

// ---------------- helpers ----------------------------------------------------
__device__ __forceinline__ uint32_t smem_u32(const void* p) {
    uint32_t a;
    asm("{ .reg .u64 t; cvta.to.shared.u64 t, %1; cvt.u32.u64 %0, t; }"
        : "=r"(a) : "l"(p));
    return a;
}
__device__ __forceinline__ unsigned ld_acq(unsigned* p) {
    unsigned v;
    asm volatile("ld.acquire.gpu.u32 %0, [%1];" : "=r"(v) : "l"(p) : "memory");
    return v;
}
__device__ __forceinline__ float4 ldcg4(const float4* p) {
    float4 v;
    asm volatile("ld.global.cg.v4.f32 {%0,%1,%2,%3}, [%4];"
                 : "=f"(v.x), "=f"(v.y), "=f"(v.z), "=f"(v.w) : "l"(p));
    return v;
}
__device__ __forceinline__ void cp16(uint32_t dst, const void* src) {
    asm volatile("cp.async.cg.shared.global [%0], [%1], 16;"
                 :: "r"(dst), "l"(src) : "memory");
}
__device__ __forceinline__ void cp_commit() {
    asm volatile("cp.async.commit_group;" ::: "memory");
}
__device__ __forceinline__ void cp_wait2() {
    asm volatile("cp.async.wait_group 2;" ::: "memory");
}
__device__ __forceinline__ void ldm_x4(uint32_t* r, uint32_t addr) {
    asm volatile("ldmatrix.sync.aligned.m8n8.x4.shared.b16 {%0,%1,%2,%3}, [%4];"
                 : "=r"(r[0]), "=r"(r[1]), "=r"(r[2]), "=r"(r[3]) : "r"(addr));
}
__device__ __forceinline__ void mma16816(float* d, const uint32_t* a, const uint32_t* b) {
    asm volatile(
        "mma.sync.aligned.m16n8k16.row.col.f32.bf16.bf16.f32 "
        "{%0,%1,%2,%3}, {%4,%5,%6,%7}, {%8,%9}, {%0,%1,%2,%3};"
        : "+f"(d[0]), "+f"(d[1]), "+f"(d[2]), "+f"(d[3])
        : "r"(a[0]), "r"(a[1]), "r"(a[2]), "r"(a[3]), "r"(b[0]), "r"(b[1]));
}

// ---------------- fp32 -> bf16 hi/lo split -----------------------------------
__global__ __launch_bounds__(256)
void split_bf16(const float* __restrict__ src, __nv_bfloat16* __restrict__ hi,
                __nv_bfloat16* __restrict__ lo, int n4)
{
    int i = blockIdx.x * 256 + threadIdx.x;
    if (i >= n4) return;
    float4 v = ((const float4*)src)[i];
    __nv_bfloat16 h0 = __float2bfloat16(v.x);
    __nv_bfloat16 h1 = __float2bfloat16(v.y);
    __nv_bfloat16 h2 = __float2bfloat16(v.z);
    __nv_bfloat16 h3 = __float2bfloat16(v.w);
    __nv_bfloat162* hp = (__nv_bfloat162*)hi;
    __nv_bfloat162* lp = (__nv_bfloat162*)lo;
    hp[2 * i + 0] = __nv_bfloat162(h0, h1);
    hp[2 * i + 1] = __nv_bfloat162(h2, h3);
    lp[2 * i + 0] = __nv_bfloat162(__float2bfloat16(v.x - __bfloat162float(h0)),
                                   __float2bfloat16(v.y - __bfloat162float(h1)));
    lp[2 * i + 1] = __nv_bfloat162(__float2bfloat16(v.z - __bfloat162float(h2)),
                                   __float2bfloat16(v.w - __bfloat162float(h3)));
}

// ---------------- barrier state init ------------------------------------------
__global__ void init_barrier() {
    if (threadIdx.x == 0) { g_cnt = 0; g_gen = 0; }
}

// ---------------- mma.sync bf16x3 GEMM: C = A*B^T + bias ----------------------
// A: [M,K] hi/lo bf16 (rows optionally gathered), B: [N,K] hi/lo bf16.
// CTA tile 128x128, BK=64 (128B rows, XOR-16B-chunk swizzle), 3-stage cp.async.
// 8 warps: warp_m = wid>>2 (2), warp_n = wid&3 (4); warp tile 64x32.
// Accumulate Ah*Bh + Ah*Bl + Al*Bh in fp32 (3xBF16 ~ fp32 accuracy).
#define BKC 64
#define TILEB 16384                      // 128 rows x 128B
#define STAGEB (4 * TILEB)               // Ah, Al, Bh, Bl
#define NSTAGE 3

__global__ __launch_bounds__(256, 1)
void bgemm_mma(const __nv_bfloat16* __restrict__ Ah, const __nv_bfloat16* __restrict__ Al,
               const __nv_bfloat16* __restrict__ Bh, const __nv_bfloat16* __restrict__ Bl,
               const float* __restrict__ bias, float* __restrict__ C,
               int N, int K, const int* __restrict__ gather)
{
    extern __shared__ char smraw[];
    const uint32_t sbase = smem_u32(smraw);

    const int tid  = threadIdx.x;
    const int lane = tid & 31;
    const int wid  = tid >> 5;
    const int warp_m = wid >> 2;         // 0..1
    const int warp_n = wid & 3;          // 0..3
    const int bm = blockIdx.x * 128;
    const int bn = blockIdx.y * 128;
    const int nchunk = K / BKC;

    // gathered A row indices for this thread's 4 load rows
    int arows[4];
#pragma unroll
    for (int q = 0; q < 4; q++) {
        int row = (q * 256 + tid) >> 3;
        int am = bm + row;
        arows[q] = gather ? ((am < BB) ? gather[am] : gather[am - BB]) : am;
    }

    auto load_stage = [&](int c) {
        const uint32_t sb = sbase + (uint32_t)(c % NSTAGE) * STAGEB;
        const int koff = c * BKC;
#pragma unroll
        for (int q = 0; q < 4; q++) {
            int idx = q * 256 + tid;
            int row = idx >> 3;
            int ch  = idx & 7;
            uint32_t dof = (uint32_t)(row * 128 + ((ch ^ (row & 7)) << 4));
            int ke = koff + ch * 8;
            cp16(sb + 0 * TILEB + dof, Ah + (size_t)arows[q] * K + ke);
            cp16(sb + 1 * TILEB + dof, Al + (size_t)arows[q] * K + ke);
            cp16(sb + 2 * TILEB + dof, Bh + (size_t)(bn + row) * K + ke);
            cp16(sb + 3 * TILEB + dof, Bl + (size_t)(bn + row) * K + ke);
        }
        cp_commit();
    };

    load_stage(0);
    load_stage(1);
    load_stage(2);

    float acc[4][4][4];
#pragma unroll
    for (int mt = 0; mt < 4; mt++)
#pragma unroll
        for (int nt = 0; nt < 4; nt++)
#pragma unroll
            for (int e = 0; e < 4; e++) acc[mt][nt][e] = 0.f;

    const int g = lane >> 3;             // ldmatrix address group
    const int r = lane & 7;

    for (int c = 0; c < nchunk; c++) {
        cp_wait2();
        __syncthreads();
        const uint32_t sb = sbase + (uint32_t)(c % NSTAGE) * STAGEB;
        const uint32_t tAh = sb, tAl = sb + TILEB, tBh = sb + 2 * TILEB, tBl = sb + 3 * TILEB;

#pragma unroll
        for (int ks = 0; ks < 4; ks++) {
            // A fragments: groups g0:(m0-7,klo) g1:(m8-15,klo) g2:(m0-7,khi) g3:(m8-15,khi)
            uint32_t ah[4][4], al[4][4];
#pragma unroll
            for (int mt = 0; mt < 4; mt++) {
                int row = warp_m * 64 + mt * 16 + ((g & 1) << 3) + r;
                int ch  = 2 * ks + (g >> 1);
                uint32_t a = (uint32_t)(row * 128 + ((ch ^ (row & 7)) << 4));
                ldm_x4(ah[mt], tAh + a);
                ldm_x4(al[mt], tAl + a);
            }
            // B fragments: x4 covers 2 n-tiles: g0:(n0-7,klo) g1:(n0-7,khi) g2:(n8-15,klo) g3:(n8-15,khi)
            uint32_t bh[4][2], bl[4][2];
#pragma unroll
            for (int np = 0; np < 2; np++) {
                int row = warp_n * 32 + np * 16 + ((g >> 1) << 3) + r;
                int ch  = 2 * ks + (g & 1);
                uint32_t a = (uint32_t)(row * 128 + ((ch ^ (row & 7)) << 4));
                uint32_t t0[4], t1[4];
                ldm_x4(t0, tBh + a);
                ldm_x4(t1, tBl + a);
                bh[2 * np][0] = t0[0]; bh[2 * np][1] = t0[1];
                bh[2 * np + 1][0] = t0[2]; bh[2 * np + 1][1] = t0[3];
                bl[2 * np][0] = t1[0]; bl[2 * np][1] = t1[1];
                bl[2 * np + 1][0] = t1[2]; bl[2 * np + 1][1] = t1[3];
            }
#pragma unroll
            for (int mt = 0; mt < 4; mt++)
#pragma unroll
                for (int nt = 0; nt < 4; nt++) {
                    mma16816(acc[mt][nt], ah[mt], bh[nt]);
                    mma16816(acc[mt][nt], ah[mt], bl[nt]);
                    mma16816(acc[mt][nt], al[mt], bh[nt]);
                }
        }
        __syncthreads();
        if (c + NSTAGE < nchunk) load_stage(c + NSTAGE);
        else cp_commit();                 // keep group accounting uniform
    }

    // epilogue: acc (mt,nt): rows bm+warp_m*64+mt*16+{lane/4, +8}, cols bn+warp_n*32+nt*8+2*(lane%4)
#pragma unroll
    for (int mt = 0; mt < 4; mt++) {
        int row0 = bm + warp_m * 64 + mt * 16 + (lane >> 2);
#pragma unroll
        for (int nt = 0; nt < 4; nt++) {
            int col = bn + warp_n * 32 + nt * 8 + ((lane & 3) << 1);
            float b0 = bias[col], b1 = bias[col + 1];
            float2 v0 = make_float2(acc[mt][nt][0] + b0, acc[mt][nt][1] + b1);
            float2 v1 = make_float2(acc[mt][nt][2] + b0, acc[mt][nt][3] + b1);
            *(float2*)(C + (size_t)row0 * N + col) = v0;
            *(float2*)(C + (size_t)(row0 + 8) * N + col) = v1;
        }
    }
}

// ---------------- persistent GRU recurrence (R3, passing version) -------------
__global__ __launch_bounds__(256, 1)
void gru_persistent(const float* __restrict__ w_hh,
                    const float* __restrict__ b_hh,
                    const float* __restrict__ gx,
                    float* __restrict__ hall,
                    float* __restrict__ hidden)
{
    extern __shared__ float smem[];
    float* w_s = smem;
    float* h_s = smem + 24 * 1024;
    float* red = h_s;

    const int tid = threadIdx.x;
    const int c = blockIdx.x;

    for (int idx = tid; idx < 24 * 256; idx += 256) {
        int rr = idx >> 8;
        int kq = idx & 255;
        int uu = rr / 3, gg = rr % 3;
        int j = c * 8 + uu;
        float4 v = *(const float4*)(w_hh + ((size_t)(gg * HH + j)) * HH + kq * 4);
        *(float4*)&w_s[rr * HH + kq * 4] = v;
    }
    for (int idx = tid; idx < HH * (BB / 4); idx += 256)
        *(float4*)&h_s[idx * 4] = make_float4(0.f, 0.f, 0.f, 0.f);
    __syncthreads();

    const int warp = tid >> 5, lane = tid & 31;
    const int pair = warp & 3, khalf = warp >> 2;
    const int kg = lane >> 3, bg = lane & 7;
    const int j0 = c * 8 + pair * 2;

    float bh[2][3];
#pragma unroll
    for (int u = 0; u < 2; u++)
#pragma unroll
        for (int gg = 0; gg < 3; gg++)
            bh[u][gg] = b_hh[gg * HH + j0 + u];

    unsigned gen_base = 0;
    if (tid == 0) gen_base = ld_acq(&g_gen);

    for (int t = 0; t < TT; t++) {
        float acc[2][3][4];
#pragma unroll
        for (int u = 0; u < 2; u++)
#pragma unroll
            for (int gg = 0; gg < 3; gg++)
#pragma unroll
                for (int b = 0; b < 4; b++) acc[u][gg][b] = 0.f;

        const int kofs = khalf * 512 + kg * 4;
        const float* w0 = &w_s[(pair * 2 + 0) * 3 * HH];
        const float* w1 = &w_s[(pair * 2 + 1) * 3 * HH];

        for (int i = 0; i < 32; i++) {
            const int k = kofs + i * 16;
            float hm[4][4];
#pragma unroll
            for (int m = 0; m < 4; m++)
                *(float4*)hm[m] = *(const float4*)&h_s[(k + m) * BB + bg * 4];
            float wv[2][3][4];
#pragma unroll
            for (int gg = 0; gg < 3; gg++) {
                *(float4*)wv[0][gg] = *(const float4*)&w0[gg * HH + k];
                *(float4*)wv[1][gg] = *(const float4*)&w1[gg * HH + k];
            }
#pragma unroll
            for (int u = 0; u < 2; u++)
#pragma unroll
                for (int gg = 0; gg < 3; gg++)
#pragma unroll
                    for (int b = 0; b < 4; b++)
                        acc[u][gg][b] += hm[0][b] * wv[u][gg][0]
                                       + hm[1][b] * wv[u][gg][1]
                                       + hm[2][b] * wv[u][gg][2]
                                       + hm[3][b] * wv[u][gg][3];
        }

#pragma unroll
        for (int u = 0; u < 2; u++)
#pragma unroll
            for (int gg = 0; gg < 3; gg++)
#pragma unroll
                for (int b = 0; b < 4; b++) {
                    float v = acc[u][gg][b];
                    v += __shfl_xor_sync(0xffffffffu, v, 8);
                    v += __shfl_xor_sync(0xffffffffu, v, 16);
                    acc[u][gg][b] = v;
                }

        float hold[2][4];
        if (lane < 8) {
#pragma unroll
            for (int u = 0; u < 2; u++)
#pragma unroll
                for (int b = 0; b < 4; b++)
                    hold[u][b] = h_s[(j0 + u) * BB + bg * 4 + b];
        }
        __syncthreads();

        if (khalf == 1 && lane < 8) {
#pragma unroll
            for (int u = 0; u < 2; u++)
#pragma unroll
                for (int gg = 0; gg < 3; gg++)
#pragma unroll
                    for (int b = 0; b < 4; b++)
                        red[pair * 192 + bg * 24 + u * 12 + gg * 4 + b] = acc[u][gg][b];
        }
        __syncthreads();

        if (khalf == 0 && lane < 8) {
#pragma unroll
            for (int u = 0; u < 2; u++) {
                const int j = j0 + u;
#pragma unroll
                for (int b4 = 0; b4 < 4; b4++) {
                    const int b = bg * 4 + b4;
                    float hr = acc[u][0][b4] + red[pair * 192 + bg * 24 + u * 12 + 0 * 4 + b4] + bh[u][0];
                    float hz = acc[u][1][b4] + red[pair * 192 + bg * 24 + u * 12 + 1 * 4 + b4] + bh[u][1];
                    float hn = acc[u][2][b4] + red[pair * 192 + bg * 24 + u * 12 + 2 * 4 + b4] + bh[u][2];

                    const float* gxp = gx + ((size_t)t * BB + b) * GG;
                    float xr = gxp[j];
                    float xz = gxp[HH + j];
                    float xn = gxp[2 * HH + j];

                    float rr = 1.f / (1.f + expf(-(xr + hr)));
                    float zz = 1.f / (1.f + expf(-(xz + hz)));
                    float nn = tanhf(xn + rr * hn);
                    float hnew = (1.f - zz) * nn + zz * hold[u][b4];

                    hall[((size_t)t * BB + b) * HH + j] = hnew;
                    g_hT[t & 1][j * BB + b] = hnew;
                    if (t == TT - 1) hidden[b * HH + j] = hnew;
                }
            }
        }

        __threadfence();
        __syncthreads();
        if (tid == 0) {
            if (atomicAdd(&g_cnt, 1u) == NCTA - 1) {
                atomicExch(&g_cnt, 0u);
                __threadfence();
                atomicAdd(&g_gen, 1u);
            }
            unsigned target = gen_base + (unsigned)(t + 1);
            while ((int)(ld_acq(&g_gen) - target) < 0) {}
        }
        __syncthreads();

        if (t < TT - 1) {
            const float* hT = &g_hT[t & 1][0];
            for (int idx = tid; idx < HH * (BB / 4); idx += 256) {
                float4 v = ldcg4((const float4*)(hT + idx * 4));
                *(float4*)&h_s[idx * 4] = v;
            }
            __syncthreads();
        }
    }
}

// ---------------- launch -------------------------------------------------------
extern "C" void kernel_launch(void* const* d_in, const int* in_sizes, int n_in,
                              void* d_out, int out_size)
{
    const int*   inputs = (const int*)  d_in[0];
    const float* emb    = (const float*)d_in[3];
    const float* w_ih   = (const float*)d_in[4];
    const float* w_hh   = (const float*)d_in[5];
    const float* b_ih   = (const float*)d_in[6];
    const float* b_hh   = (const float*)d_in[7];
    const float* out_w  = (const float*)d_in[8];
    const float* out_b  = (const float*)d_in[9];

    float* logits = (float*)d_out;
    float* hidden = (float*)d_out + (size_t)MM * VV;

    float* gx;   cudaGetSymbolAddress((void**)&gx,   g_gx);
    float* hall; cudaGetSymbolAddress((void**)&hall, g_hall);
    __nv_bfloat16 *Ah, *Al, *Bh, *Bl, *Wh, *Wl;
    cudaGetSymbolAddress((void**)&Ah, g_Ah);
    cudaGetSymbolAddress((void**)&Al, g_Al);
    cudaGetSymbolAddress((void**)&Bh, g_Bh);
    cudaGetSymbolAddress((void**)&Bl, g_Bl);
    cudaGetSymbolAddress((void**)&Wh, g_Wh);
    cudaGetSymbolAddress((void**)&Wl, g_Wl);

    const int gemm_smem = NSTAGE * STAGEB;   // 196608
    cudaFuncSetAttribute(bgemm_mma, cudaFuncAttributeMaxDynamicSharedMemorySize, gemm_smem);

    // 0-2: splits of all weights
    split_bf16<<<(VV * EE / 4 + 255) / 256, 256>>>(emb, Ah, Al, VV * EE / 4);
    split_bf16<<<(GG * EE / 4 + 255) / 256, 256>>>(w_ih, Wh, Wl, GG * EE / 4);
    split_bf16<<<(VV * HH / 4 + 255) / 256, 256>>>(out_w, Bh, Bl, VV * HH / 4);

    // 3: gx = emb[x_idx] @ w_ih^T + b_ih
    {
        dim3 grid(MM / 128, GG / 128);   // (32, 24), m fastest
        bgemm_mma<<<grid, 256, gemm_smem>>>(Ah, Al, Wh, Wl, b_ih, gx, GG, EE, inputs);
    }

    // 4: barrier state init (also positions gru at ncu capture index 5)
    init_barrier<<<1, 32>>>();

    // 5: GRU recurrence (persistent)
    {
        const int smem = (24 * HH + HH * BB) * sizeof(float);
        cudaFuncSetAttribute(gru_persistent,
                             cudaFuncAttributeMaxDynamicSharedMemorySize, smem);
        gru_persistent<<<NCTA, 256, smem>>>(w_hh, b_hh, gx, hall, hidden);
    }

    // 6: split hall (reuse emb split buffers)
    split_bf16<<<(MM * HH / 4 + 255) / 256, 256>>>(hall, Ah, Al, MM * HH / 4);

    // 7: logits = hall @ out_w^T + out_b
    {
        dim3 grid(MM / 128, VV / 128);   // (32, 250), m fastest
        bgemm_mma<<<grid, 256, gemm_smem>>>(Ah, Al, Bh, Bl, out_b, logits, VV, HH, nullptr);
    }
}

// round 6
// speedup vs baseline: 3.0079x; 1.0110x over previous
#include <cuda_runtime.h>
#include <cuda_bf16.h>
#include <math.h>
#include <stdint.h>

// Problem dims
#define TT 128
#define BB 32
#define EE 512
#define HH 1024
#define VV 32000
#define GG (3 * HH)       // 3072
#define MM (TT * BB)      // 4096
#define NCTA 128

// ---------------- scratch (device globals) ----------------------------------
__device__ float g_gx[MM * GG];                // [T*B, 3H]
__device__ float g_hall[MM * HH];              // [T*B, H]
__device__ float g_hT[2][HH * BB];             // ping-pong transposed hidden
__device__ unsigned g_cnt = 0;
__device__ unsigned g_gen = 0;
__device__ __nv_bfloat16 g_Ah[VV * EE];        // emb split, then hall split
__device__ __nv_bfloat16 g_Al[VV * EE];
__device__ __nv_bfloat16 g_Bh[VV * HH];        // out_w split
__device__ __nv_bfloat16 g_Bl[VV * HH];
__device__ __nv_bfloat16 g_Wh[GG * EE];        // w_ih split
__device__ __nv_bfloat16 g_Wl[GG * EE];

// ---------------- helpers ----------------------------------------------------
__device__ __forceinline__ uint32_t smem_u32(const void* p) {
    uint32_t a;
    asm("{ .reg .u64 t; cvta.to.shared.u64 t, %1; cvt.u32.u64 %0, t; }"
        : "=r"(a) : "l"(p));
    return a;
}
__device__ __forceinline__ unsigned ld_acq(unsigned* p) {
    unsigned v;
    asm volatile("ld.acquire.gpu.u32 %0, [%1];" : "=r"(v) : "l"(p) : "memory");
    return v;
}
__device__ __forceinline__ float4 ldcg4(const float4* p) {
    float4 v;
    asm volatile("ld.global.cg.v4.f32 {%0,%1,%2,%3}, [%4];"
                 : "=f"(v.x), "=f"(v.y), "=f"(v.z), "=f"(v.w) : "l"(p));
    return v;
}
__device__ __forceinline__ void cp16(uint32_t dst, const void* src) {
    asm volatile("cp.async.cg.shared.global [%0], [%1], 16;"
                 :: "r"(dst), "l"(src) : "memory");
}
__device__ __forceinline__ void cp_commit() {
    asm volatile("cp.async.commit_group;" ::: "memory");
}
__device__ __forceinline__ void cp_wait1() {
    asm volatile("cp.async.wait_group 1;" ::: "memory");
}
__device__ __forceinline__ void ldm_x4(uint32_t* r, uint32_t addr) {
    asm volatile("ldmatrix.sync.aligned.m8n8.x4.shared.b16 {%0,%1,%2,%3}, [%4];"
                 : "=r"(r[0]), "=r"(r[1]), "=r"(r[2]), "=r"(r[3]) : "r"(addr));
}
__device__ __forceinline__ void mma16816(float* d, const uint32_t* a, const uint32_t* b) {
    asm volatile(
        "mma.sync.aligned.m16n8k16.row.col.f32.bf16.bf16.f32 "
        "{%0,%1,%2,%3}, {%4,%5,%6,%7}, {%8,%9}, {%0,%1,%2,%3};"
        : "+f"(d[0]), "+f"(d[1]), "+f"(d[2]), "+f"(d[3])
        : "r"(a[0]), "r"(a[1]), "r"(a[2]), "r"(a[3]), "r"(b[0]), "r"(b[1]));
}

// ---------------- fp32 -> bf16 hi/lo split -----------------------------------
__global__ __launch_bounds__(256)
void split_bf16(const float* __restrict__ src, __nv_bfloat16* __restrict__ hi,
                __nv_bfloat16* __restrict__ lo, int n4)
{
    int i = blockIdx.x * 256 + threadIdx.x;
    if (i >= n4) return;
    float4 v = ((const float4*)src)[i];
    __nv_bfloat16 h0 = __float2bfloat16(v.x);
    __nv_bfloat16 h1 = __float2bfloat16(v.y);
    __nv_bfloat16 h2 = __float2bfloat16(v.z);
    __nv_bfloat16 h3 = __float2bfloat16(v.w);
    __nv_bfloat162* hp = (__nv_bfloat162*)hi;
    __nv_bfloat162* lp = (__nv_bfloat162*)lo;
    hp[2 * i + 0] = __nv_bfloat162(h0, h1);
    hp[2 * i + 1] = __nv_bfloat162(h2, h3);
    lp[2 * i + 0] = __nv_bfloat162(__float2bfloat16(v.x - __bfloat162float(h0)),
                                   __float2bfloat16(v.y - __bfloat162float(h1)));
    lp[2 * i + 1] = __nv_bfloat162(__float2bfloat16(v.z - __bfloat162float(h2)),
                                   __float2bfloat16(v.w - __bfloat162float(h3)));
}

// ---------------- barrier state init ------------------------------------------
__global__ void init_barrier() {
    if (threadIdx.x == 0) { g_cnt = 0; g_gen = 0; }
}

// ---------------- mma.sync bf16x3 GEMM: C = A*B^T + bias ----------------------
// CTA tile 128x128, BK=64, 3-stage cp.async, ONE sync per chunk:
//   wait_group(1) -> stage c ready; sync; issue loads for stage c+2 (overwrites
//   the stage compute(c-1) just finished reading -- safe after the sync);
//   then compute(c) overlapping the in-flight copies.
#define BKC 64
#define TILEB 16384                      // 128 rows x 128B
#define STAGEB (4 * TILEB)               // Ah, Al, Bh, Bl
#define NSTAGE 3

__global__ __launch_bounds__(256, 1)
void bgemm_mma(const __nv_bfloat16* __restrict__ Ah, const __nv_bfloat16* __restrict__ Al,
               const __nv_bfloat16* __restrict__ Bh, const __nv_bfloat16* __restrict__ Bl,
               const float* __restrict__ bias, float* __restrict__ C,
               int N, int K, const int* __restrict__ gather)
{
    extern __shared__ char smraw[];
    const uint32_t sbase = smem_u32(smraw);

    const int tid  = threadIdx.x;
    const int lane = tid & 31;
    const int wid  = tid >> 5;
    const int warp_m = wid >> 2;         // 0..1
    const int warp_n = wid & 3;          // 0..3
    const int bm = blockIdx.x * 128;
    const int bn = blockIdx.y * 128;
    const int nchunk = K / BKC;

    // gathered A row indices for this thread's 4 load rows
    int arows[4];
#pragma unroll
    for (int q = 0; q < 4; q++) {
        int row = (q * 256 + tid) >> 3;
        int am = bm + row;
        arows[q] = gather ? ((am < BB) ? gather[am] : gather[am - BB]) : am;
    }
    // precomputed per-thread source/dest offsets
    const int ch0  = tid & 7;
    uint32_t dof[4];
    const __nv_bfloat16* bsrc[4];
#pragma unroll
    for (int q = 0; q < 4; q++) {
        int row = (q * 256 + tid) >> 3;
        dof[q] = (uint32_t)(row * 128 + ((ch0 ^ (row & 7)) << 4));
        bsrc[q] = /* filled per use */ nullptr;
        (void)bsrc;
    }

    auto load_stage = [&](int c) {
        const uint32_t sb = sbase + (uint32_t)(c % NSTAGE) * STAGEB;
        const int ke0 = c * BKC + ch0 * 8;
#pragma unroll
        for (int q = 0; q < 4; q++) {
            int row = (q * 256 + tid) >> 3;
            cp16(sb + 0 * TILEB + dof[q], Ah + (size_t)arows[q] * K + ke0);
            cp16(sb + 1 * TILEB + dof[q], Al + (size_t)arows[q] * K + ke0);
            cp16(sb + 2 * TILEB + dof[q], Bh + (size_t)(bn + row) * K + ke0);
            cp16(sb + 3 * TILEB + dof[q], Bl + (size_t)(bn + row) * K + ke0);
        }
        cp_commit();
    };

    load_stage(0);
    if (nchunk > 1) load_stage(1); else cp_commit();

    float acc[4][4][4];
#pragma unroll
    for (int mt = 0; mt < 4; mt++)
#pragma unroll
        for (int nt = 0; nt < 4; nt++)
#pragma unroll
            for (int e = 0; e < 4; e++) acc[mt][nt][e] = 0.f;

    const int g = lane >> 3;
    const int r = lane & 7;

    // precompute ldmatrix smem offsets (stage-relative)
    uint32_t aoff[4][4], boff[2][4];     // [mt or np][ks]
#pragma unroll
    for (int ks = 0; ks < 4; ks++) {
#pragma unroll
        for (int mt = 0; mt < 4; mt++) {
            int row = warp_m * 64 + mt * 16 + ((g & 1) << 3) + r;
            int ch  = 2 * ks + (g >> 1);
            aoff[mt][ks] = (uint32_t)(row * 128 + ((ch ^ (row & 7)) << 4));
        }
#pragma unroll
        for (int np = 0; np < 2; np++) {
            int row = warp_n * 32 + np * 16 + ((g >> 1) << 3) + r;
            int ch  = 2 * ks + (g & 1);
            boff[np][ks] = (uint32_t)(row * 128 + ((ch ^ (row & 7)) << 4));
        }
    }

    for (int c = 0; c < nchunk; c++) {
        cp_wait1();
        __syncthreads();
        // issue next stage's copies FIRST so they overlap this chunk's MMAs
        if (c + 2 < nchunk) load_stage(c + 2);
        else cp_commit();

        const uint32_t sb = sbase + (uint32_t)(c % NSTAGE) * STAGEB;
        const uint32_t tAh = sb, tAl = sb + TILEB, tBh = sb + 2 * TILEB, tBl = sb + 3 * TILEB;

#pragma unroll
        for (int ks = 0; ks < 4; ks++) {
            uint32_t ah[4][4], al[4][4];
#pragma unroll
            for (int mt = 0; mt < 4; mt++) {
                ldm_x4(ah[mt], tAh + aoff[mt][ks]);
                ldm_x4(al[mt], tAl + aoff[mt][ks]);
            }
            uint32_t bh[4][2], bl[4][2];
#pragma unroll
            for (int np = 0; np < 2; np++) {
                uint32_t t0[4], t1[4];
                ldm_x4(t0, tBh + boff[np][ks]);
                ldm_x4(t1, tBl + boff[np][ks]);
                bh[2 * np][0] = t0[0]; bh[2 * np][1] = t0[1];
                bh[2 * np + 1][0] = t0[2]; bh[2 * np + 1][1] = t0[3];
                bl[2 * np][0] = t1[0]; bl[2 * np][1] = t1[1];
                bl[2 * np + 1][0] = t1[2]; bl[2 * np + 1][1] = t1[3];
            }
#pragma unroll
            for (int mt = 0; mt < 4; mt++)
#pragma unroll
                for (int nt = 0; nt < 4; nt++) {
                    mma16816(acc[mt][nt], ah[mt], bh[nt]);
                    mma16816(acc[mt][nt], ah[mt], bl[nt]);
                    mma16816(acc[mt][nt], al[mt], bh[nt]);
                }
        }
    }

    // epilogue
#pragma unroll
    for (int mt = 0; mt < 4; mt++) {
        int row0 = bm + warp_m * 64 + mt * 16 + (lane >> 2);
#pragma unroll
        for (int nt = 0; nt < 4; nt++) {
            int col = bn + warp_n * 32 + nt * 8 + ((lane & 3) << 1);
            float b0 = bias[col], b1 = bias[col + 1];
            float2 v0 = make_float2(acc[mt][nt][0] + b0, acc[mt][nt][1] + b1);
            float2 v1 = make_float2(acc[mt][nt][2] + b0, acc[mt][nt][3] + b1);
            *(float2*)(C + (size_t)row0 * N + col) = v0;
            *(float2*)(C + (size_t)(row0 + 8) * N + col) = v1;
        }
    }
}

// ---------------- persistent GRU recurrence (unchanged, passing) --------------
__global__ __launch_bounds__(256, 1)
void gru_persistent(const float* __restrict__ w_hh,
                    const float* __restrict__ b_hh,
                    const float* __restrict__ gx,
                    float* __restrict__ hall,
                    float* __restrict__ hidden)
{
    extern __shared__ float smem[];
    float* w_s = smem;
    float* h_s = smem + 24 * 1024;
    float* red = h_s;

    const int tid = threadIdx.x;
    const int c = blockIdx.x;

    for (int idx = tid; idx < 24 * 256; idx += 256) {
        int rr = idx >> 8;
        int kq = idx & 255;
        int uu = rr / 3, gg = rr % 3;
        int j = c * 8 + uu;
        float4 v = *(const float4*)(w_hh + ((size_t)(gg * HH + j)) * HH + kq * 4);
        *(float4*)&w_s[rr * HH + kq * 4] = v;
    }
    for (int idx = tid; idx < HH * (BB / 4); idx += 256)
        *(float4*)&h_s[idx * 4] = make_float4(0.f, 0.f, 0.f, 0.f);
    __syncthreads();

    const int warp = tid >> 5, lane = tid & 31;
    const int pair = warp & 3, khalf = warp >> 2;
    const int kg = lane >> 3, bg = lane & 7;
    const int j0 = c * 8 + pair * 2;

    float bh[2][3];
#pragma unroll
    for (int u = 0; u < 2; u++)
#pragma unroll
        for (int gg = 0; gg < 3; gg++)
            bh[u][gg] = b_hh[gg * HH + j0 + u];

    unsigned gen_base = 0;
    if (tid == 0) gen_base = ld_acq(&g_gen);

    for (int t = 0; t < TT; t++) {
        float acc[2][3][4];
#pragma unroll
        for (int u = 0; u < 2; u++)
#pragma unroll
            for (int gg = 0; gg < 3; gg++)
#pragma unroll
                for (int b = 0; b < 4; b++) acc[u][gg][b] = 0.f;

        const int kofs = khalf * 512 + kg * 4;
        const float* w0 = &w_s[(pair * 2 + 0) * 3 * HH];
        const float* w1 = &w_s[(pair * 2 + 1) * 3 * HH];

        for (int i = 0; i < 32; i++) {
            const int k = kofs + i * 16;
            float hm[4][4];
#pragma unroll
            for (int m = 0; m < 4; m++)
                *(float4*)hm[m] = *(const float4*)&h_s[(k + m) * BB + bg * 4];
            float wv[2][3][4];
#pragma unroll
            for (int gg = 0; gg < 3; gg++) {
                *(float4*)wv[0][gg] = *(const float4*)&w0[gg * HH + k];
                *(float4*)wv[1][gg] = *(const float4*)&w1[gg * HH + k];
            }
#pragma unroll
            for (int u = 0; u < 2; u++)
#pragma unroll
                for (int gg = 0; gg < 3; gg++)
#pragma unroll
                    for (int b = 0; b < 4; b++)
                        acc[u][gg][b] += hm[0][b] * wv[u][gg][0]
                                       + hm[1][b] * wv[u][gg][1]
                                       + hm[2][b] * wv[u][gg][2]
                                       + hm[3][b] * wv[u][gg][3];
        }

#pragma unroll
        for (int u = 0; u < 2; u++)
#pragma unroll
            for (int gg = 0; gg < 3; gg++)
#pragma unroll
                for (int b = 0; b < 4; b++) {
                    float v = acc[u][gg][b];
                    v += __shfl_xor_sync(0xffffffffu, v, 8);
                    v += __shfl_xor_sync(0xffffffffu, v, 16);
                    acc[u][gg][b] = v;
                }

        float hold[2][4];
        if (lane < 8) {
#pragma unroll
            for (int u = 0; u < 2; u++)
#pragma unroll
                for (int b = 0; b < 4; b++)
                    hold[u][b] = h_s[(j0 + u) * BB + bg * 4 + b];
        }
        __syncthreads();

        if (khalf == 1 && lane < 8) {
#pragma unroll
            for (int u = 0; u < 2; u++)
#pragma unroll
                for (int gg = 0; gg < 3; gg++)
#pragma unroll
                    for (int b = 0; b < 4; b++)
                        red[pair * 192 + bg * 24 + u * 12 + gg * 4 + b] = acc[u][gg][b];
        }
        __syncthreads();

        if (khalf == 0 && lane < 8) {
#pragma unroll
            for (int u = 0; u < 2; u++) {
                const int j = j0 + u;
#pragma unroll
                for (int b4 = 0; b4 < 4; b4++) {
                    const int b = bg * 4 + b4;
                    float hr = acc[u][0][b4] + red[pair * 192 + bg * 24 + u * 12 + 0 * 4 + b4] + bh[u][0];
                    float hz = acc[u][1][b4] + red[pair * 192 + bg * 24 + u * 12 + 1 * 4 + b4] + bh[u][1];
                    float hn = acc[u][2][b4] + red[pair * 192 + bg * 24 + u * 12 + 2 * 4 + b4] + bh[u][2];

                    const float* gxp = gx + ((size_t)t * BB + b) * GG;
                    float xr = gxp[j];
                    float xz = gxp[HH + j];
                    float xn = gxp[2 * HH + j];

                    float rr = 1.f / (1.f + expf(-(xr + hr)));
                    float zz = 1.f / (1.f + expf(-(xz + hz)));
                    float nn = tanhf(xn + rr * hn);
                    float hnew = (1.f - zz) * nn + zz * hold[u][b4];

                    hall[((size_t)t * BB + b) * HH + j] = hnew;
                    g_hT[t & 1][j * BB + b] = hnew;
                    if (t == TT - 1) hidden[b * HH + j] = hnew;
                }
            }
        }

        __threadfence();
        __syncthreads();
        if (tid == 0) {
            if (atomicAdd(&g_cnt, 1u) == NCTA - 1) {
                atomicExch(&g_cnt, 0u);
                __threadfence();
                atomicAdd(&g_gen, 1u);
            }
            unsigned target = gen_base + (unsigned)(t + 1);
            while ((int)(ld_acq(&g_gen) - target) < 0) {}
        }
        __syncthreads();

        if (t < TT - 1) {
            const float* hT = &g_hT[t & 1][0];
            for (int idx = tid; idx < HH * (BB / 4); idx += 256) {
                float4 v = ldcg4((const float4*)(hT + idx * 4));
                *(float4*)&h_s[idx * 4] = v;
            }
            __syncthreads();
        }
    }
}

// ---------------- launch -------------------------------------------------------
extern "C" void kernel_launch(void* const* d_in, const int* in_sizes, int n_in,
                              void* d_out, int out_size)
{
    const int*   inputs = (const int*)  d_in[0];
    const float* emb    = (const float*)d_in[3];
    const float* w_ih   = (const float*)d_in[4];
    const float* w_hh   = (const float*)d_in[5];
    const float* b_ih   = (const float*)d_in[6];
    const float* b_hh   = (const float*)d_in[7];
    const float* out_w  = (const float*)d_in[8];
    const float* out_b  = (const float*)d_in[9];

    float* logits = (float*)d_out;
    float* hidden = (float*)d_out + (size_t)MM * VV;

    float* gx;   cudaGetSymbolAddress((void**)&gx,   g_gx);
    float* hall; cudaGetSymbolAddress((void**)&hall, g_hall);
    __nv_bfloat16 *Ah, *Al, *Bh, *Bl, *Wh, *Wl;
    cudaGetSymbolAddress((void**)&Ah, g_Ah);
    cudaGetSymbolAddress((void**)&Al, g_Al);
    cudaGetSymbolAddress((void**)&Bh, g_Bh);
    cudaGetSymbolAddress((void**)&Bl, g_Bl);
    cudaGetSymbolAddress((void**)&Wh, g_Wh);
    cudaGetSymbolAddress((void**)&Wl, g_Wl);

    const int gemm_smem = NSTAGE * STAGEB;   // 196608
    cudaFuncSetAttribute(bgemm_mma, cudaFuncAttributeMaxDynamicSharedMemorySize, gemm_smem);

    // 0-2: splits of all weights
    split_bf16<<<(VV * EE / 4 + 255) / 256, 256>>>(emb, Ah, Al, VV * EE / 4);
    split_bf16<<<(GG * EE / 4 + 255) / 256, 256>>>(w_ih, Wh, Wl, GG * EE / 4);
    split_bf16<<<(VV * HH / 4 + 255) / 256, 256>>>(out_w, Bh, Bl, VV * HH / 4);

    // 3: gx = emb[x_idx] @ w_ih^T + b_ih
    {
        dim3 grid(MM / 128, GG / 128);   // (32, 24), m fastest
        bgemm_mma<<<grid, 256, gemm_smem>>>(Ah, Al, Wh, Wl, b_ih, gx, GG, EE, inputs);
    }

    // 4: barrier state init
    init_barrier<<<1, 32>>>();

    // 5: GRU recurrence (persistent)
    {
        const int smem = (24 * HH + HH * BB) * sizeof(float);
        cudaFuncSetAttribute(gru_persistent,
                             cudaFuncAttributeMaxDynamicSharedMemorySize, smem);
        gru_persistent<<<NCTA, 256, smem>>>(w_hh, b_hh, gx, hall, hidden);
    }

    // 6: split hall (reuse emb split buffers)
    split_bf16<<<(MM * HH / 4 + 255) / 256, 256>>>(hall, Ah, Al, MM * HH / 4);

    // 7: logits = hall @ out_w^T + out_b
    {
        dim3 grid(MM / 128, VV / 128);   // (32, 250), m fastest
        bgemm_mma<<<grid, 256, gemm_smem>>>(Ah, Al, Bh, Bl, out_b, logits, VV, HH, nullptr);
    }
}